// round 5
// baseline (speedup 1.0000x reference)
#include <cuda_runtime.h>
#include <math.h>
#include <stdint.h>

// Problem constants
constexpr int Bb = 2;
constexpr int Tt = 2048;
constexpr int Cc = 1024;
constexpr int Hh = 16;
constexpr int Dd = 64;
constexpr int Mrows = Bb * Tt;        // 4096
constexpr int C3 = 3 * Cc;            // 3072
constexpr int BH = Bb * Hh;           // 32

// Device scratch (allocation-free rule: __device__ globals)
__device__ float g_qkv[(size_t)Mrows * C3];    // [4096, 3072]
__device__ float g_attnv[(size_t)Mrows * Cc];  // [4096, 1024]
__device__ float g_tilestats[(size_t)BH * Tt * 16 * 2]; // per (row, ktile): max, expsum

// ---------------------------------------------------------------------------
// helpers
// ---------------------------------------------------------------------------
__device__ __forceinline__ uint32_t f2tf(float f) {
    uint32_t u;
    asm("cvt.rna.tf32.f32 %0, %1;" : "=r"(u) : "f"(f));
    return u;
}

__device__ __forceinline__ void mma8(float* c, const uint32_t* a, const uint32_t* b) {
    asm volatile(
        "mma.sync.aligned.m16n8k8.row.col.f32.tf32.tf32.f32 "
        "{%0,%1,%2,%3},{%4,%5,%6,%7},{%8,%9},{%0,%1,%2,%3};"
        : "+f"(c[0]), "+f"(c[1]), "+f"(c[2]), "+f"(c[3])
        : "r"(a[0]), "r"(a[1]), "r"(a[2]), "r"(a[3]), "r"(b[0]), "r"(b[1]));
}

__device__ __forceinline__ void cpasync16(uint32_t saddr, const void* gptr) {
    asm volatile("cp.async.ca.shared.global [%0], [%1], 16;\n" ::"r"(saddr), "l"(gptr));
}

// ---------------------------------------------------------------------------
// Dense NN GEMM: C[M,N] = A[M,K] @ B[K,N] + bias[N]  (tf32, cp.async 3-stage)
// ---------------------------------------------------------------------------
__global__ __launch_bounds__(256, 2) void gemm_nn_tf32(
    const float* __restrict__ A, int lda,
    const float* __restrict__ Bm, int ldb,
    const float* __restrict__ bias,
    float* __restrict__ Cm, int ldc, int Kd)
{
    extern __shared__ float sh[];
    constexpr int STG_F = 128 * 20 + 16 * 128;  // floats per stage

    const int tid = threadIdx.x;
    const int wid = tid >> 5, lane = tid & 31;
    const int g = lane >> 2, tg = lane & 3;
    const int warp_m = wid & 1, warp_n = wid >> 1;
    const int row0 = blockIdx.y * 128;
    const int col0 = blockIdx.x * 128;

    const uint32_t shbase = (uint32_t)__cvta_generic_to_shared(sh);

    auto issue = [&](int s, int k0) {
#pragma unroll
        for (int i = 0; i < 2; i++) {
            int c = tid + i * 256;
            int m = c >> 2, kq = (c & 3) * 4;
            cpasync16(shbase + (s * STG_F + m * 20 + kq) * 4,
                      A + (size_t)(row0 + m) * lda + k0 + kq);
        }
#pragma unroll
        for (int i = 0; i < 2; i++) {
            int c = tid + i * 256;
            int k = c >> 5, nq = (c & 31) * 4;
            int nx = nq ^ ((k & 3) << 3);
            cpasync16(shbase + (s * STG_F + 128 * 20 + k * 128 + nx) * 4,
                      Bm + (size_t)(k0 + k) * ldb + col0 + nq);
        }
        asm volatile("cp.async.commit_group;\n");
    };

    const int nIter = Kd / 16;
    issue(0, 0);
    issue(1, 16);

    float acc[4][4][4] = {};

    for (int j = 0; j < nIter; j++) {
        if (j == nIter - 1) {
            asm volatile("cp.async.wait_group 0;\n");
        } else {
            asm volatile("cp.async.wait_group 1;\n");
        }
        __syncthreads();
        const float* Asj = sh + (j % 3) * STG_F;
        const float* Bsj = Asj + 128 * 20;
#pragma unroll
        for (int ks = 0; ks < 16; ks += 8) {
            uint32_t af[4][4], bf[4][2];
#pragma unroll
            for (int mi = 0; mi < 4; mi++) {
                int m = warp_m * 64 + mi * 16;
                af[mi][0] = f2tf(Asj[(m + g) * 20 + ks + tg]);
                af[mi][1] = f2tf(Asj[(m + g + 8) * 20 + ks + tg]);
                af[mi][2] = f2tf(Asj[(m + g) * 20 + ks + tg + 4]);
                af[mi][3] = f2tf(Asj[(m + g + 8) * 20 + ks + tg + 4]);
            }
            const int xr = tg << 3;
#pragma unroll
            for (int ni = 0; ni < 4; ni++) {
                int n = warp_n * 32 + ni * 8;
                bf[ni][0] = f2tf(Bsj[(ks + tg) * 128 + ((n + g) ^ xr)]);
                bf[ni][1] = f2tf(Bsj[(ks + tg + 4) * 128 + ((n + g) ^ xr)]);
            }
#pragma unroll
            for (int mi = 0; mi < 4; mi++)
#pragma unroll
                for (int ni = 0; ni < 4; ni++) mma8(acc[mi][ni], af[mi], bf[ni]);
        }
        if (j + 2 < nIter) issue((j + 2) % 3, (j + 2) * 16);
    }

#pragma unroll
    for (int mi = 0; mi < 4; mi++) {
#pragma unroll
        for (int ni = 0; ni < 4; ni++) {
            int m = row0 + warp_m * 64 + mi * 16 + g;
            int n = col0 + warp_n * 32 + ni * 8 + tg * 2;
            float2 o0 = {acc[mi][ni][0] + bias[n], acc[mi][ni][1] + bias[n + 1]};
            float2 o1 = {acc[mi][ni][2] + bias[n], acc[mi][ni][3] + bias[n + 1]};
            *(float2*)(Cm + (size_t)m * ldc + n) = o0;
            *(float2*)(Cm + (size_t)(m + 8) * ldc + n) = o1;
        }
    }
}

// ---------------------------------------------------------------------------
// Scores -> E = exp(scale*QK^T - tile_rowmax), plus per-(row,tile) stats
// (max, expsum). Upper tiles: write final zeros.
// ---------------------------------------------------------------------------
__global__ __launch_bounds__(256, 2) void scores_tf32(float* __restrict__ S)
{
    const int bh = blockIdx.z;
    const int q0 = blockIdx.y * 128;
    const int k0t = blockIdx.x * 128;
    float* Sb = S + (size_t)bh * Tt * Tt;
    const int tid = threadIdx.x;

    if (blockIdx.x > blockIdx.y) {
        const float4 z = {0.f, 0.f, 0.f, 0.f};
#pragma unroll
        for (int i = 0; i < 16; i++) {
            int f = i * 256 + tid;
            int r = f >> 5, c = (f & 31) * 4;
            *(float4*)(Sb + (size_t)(q0 + r) * Tt + k0t + c) = z;
        }
        return;
    }

    extern __shared__ uint32_t sm[];
    uint32_t* Qs = sm;                // [128][68]
    uint32_t* Ks = sm + 128 * 68;     // [128][68]
    __shared__ float sred[128][4];
    __shared__ float sredm[128];

    const int b = bh / Hh, h = bh % Hh;
    const int wid = tid >> 5, lane = tid & 31;
    const int g = lane >> 2, tg = lane & 3;
    const int warp_m = wid & 1, warp_n = wid >> 1;

    const float* Qb = g_qkv + (size_t)(b * Tt + q0) * C3 + h * Dd;
    const float* Kb = g_qkv + (size_t)(b * Tt + k0t) * C3 + Cc + h * Dd;

#pragma unroll
    for (int i = 0; i < 8; i++) {
        int f = tid + i * 256;
        int m = f >> 4, kq = (f & 15) * 4;
        float4 qv = *(const float4*)(Qb + (size_t)m * C3 + kq);
        Qs[m * 68 + kq + 0] = f2tf(qv.x);
        Qs[m * 68 + kq + 1] = f2tf(qv.y);
        Qs[m * 68 + kq + 2] = f2tf(qv.z);
        Qs[m * 68 + kq + 3] = f2tf(qv.w);
        float4 kv = *(const float4*)(Kb + (size_t)m * C3 + kq);
        Ks[m * 68 + kq + 0] = f2tf(kv.x);
        Ks[m * 68 + kq + 1] = f2tf(kv.y);
        Ks[m * 68 + kq + 2] = f2tf(kv.z);
        Ks[m * 68 + kq + 3] = f2tf(kv.w);
    }
    __syncthreads();

    float acc[4][4][4] = {};
#pragma unroll
    for (int ks = 0; ks < 64; ks += 8) {
        uint32_t af[4][4], bf[4][2];
#pragma unroll
        for (int mi = 0; mi < 4; mi++) {
            int m = warp_m * 64 + mi * 16;
            af[mi][0] = Qs[(m + g) * 68 + ks + tg];
            af[mi][1] = Qs[(m + g + 8) * 68 + ks + tg];
            af[mi][2] = Qs[(m + g) * 68 + ks + tg + 4];
            af[mi][3] = Qs[(m + g + 8) * 68 + ks + tg + 4];
        }
#pragma unroll
        for (int ni = 0; ni < 4; ni++) {
            int n = warp_n * 32 + ni * 8;
            bf[ni][0] = Ks[(n + g) * 68 + ks + tg];
            bf[ni][1] = Ks[(n + g) * 68 + ks + tg + 4];
        }
#pragma unroll
        for (int mi = 0; mi < 4; mi++)
#pragma unroll
            for (int ni = 0; ni < 4; ni++) mma8(acc[mi][ni], af[mi], bf[ni]);
    }

    // scale + diag mask
    const float scale = 0.125f;
    const bool diag = (blockIdx.x == blockIdx.y);
    const float NEG = -INFINITY;
#pragma unroll
    for (int mi = 0; mi < 4; mi++) {
        int r0 = warp_m * 64 + mi * 16 + g;
#pragma unroll
        for (int ni = 0; ni < 4; ni++) {
            int n0 = warp_n * 32 + ni * 8 + tg * 2;
            float* a = acc[mi][ni];
            a[0] *= scale; a[1] *= scale; a[2] *= scale; a[3] *= scale;
            if (diag) {
                if (n0 > r0)     a[0] = NEG;
                if (n0 + 1 > r0) a[1] = NEG;
                if (n0 > r0 + 8)     a[2] = NEG;
                if (n0 + 1 > r0 + 8) a[3] = NEG;
            }
        }
    }

    // tile rowmax
    float mx[4][2];
#pragma unroll
    for (int mi = 0; mi < 4; mi++) {
        float m0 = -INFINITY, m1 = -INFINITY;
#pragma unroll
        for (int ni = 0; ni < 4; ni++) {
            m0 = fmaxf(m0, fmaxf(acc[mi][ni][0], acc[mi][ni][1]));
            m1 = fmaxf(m1, fmaxf(acc[mi][ni][2], acc[mi][ni][3]));
        }
        m0 = fmaxf(m0, __shfl_xor_sync(0xffffffffu, m0, 1));
        m0 = fmaxf(m0, __shfl_xor_sync(0xffffffffu, m0, 2));
        m1 = fmaxf(m1, __shfl_xor_sync(0xffffffffu, m1, 1));
        m1 = fmaxf(m1, __shfl_xor_sync(0xffffffffu, m1, 2));
        mx[mi][0] = m0; mx[mi][1] = m1;
    }
    if (tg == 0) {
#pragma unroll
        for (int mi = 0; mi < 4; mi++) {
            sred[warp_m * 64 + mi * 16 + g][warp_n] = mx[mi][0];
            sred[warp_m * 64 + mi * 16 + g + 8][warp_n] = mx[mi][1];
        }
    }
    __syncthreads();
    if (tid < 128) {
        sredm[tid] = fmaxf(fmaxf(sred[tid][0], sred[tid][1]),
                           fmaxf(sred[tid][2], sred[tid][3]));
    }
    __syncthreads();

    // E = exp(a - rowmax); acc becomes E; accumulate sums
#pragma unroll
    for (int mi = 0; mi < 4; mi++) {
        float rm0 = sredm[warp_m * 64 + mi * 16 + g];
        float rm1 = sredm[warp_m * 64 + mi * 16 + g + 8];
        float s0 = 0.f, s1 = 0.f;
#pragma unroll
        for (int ni = 0; ni < 4; ni++) {
            float* a = acc[mi][ni];
            a[0] = __expf(a[0] - rm0);
            a[1] = __expf(a[1] - rm0);
            a[2] = __expf(a[2] - rm1);
            a[3] = __expf(a[3] - rm1);
            s0 += a[0] + a[1];
            s1 += a[2] + a[3];
        }
        s0 += __shfl_xor_sync(0xffffffffu, s0, 1);
        s0 += __shfl_xor_sync(0xffffffffu, s0, 2);
        s1 += __shfl_xor_sync(0xffffffffu, s1, 1);
        s1 += __shfl_xor_sync(0xffffffffu, s1, 2);
        mx[mi][0] = s0; mx[mi][1] = s1;
    }

    // write E tile
#pragma unroll
    for (int mi = 0; mi < 4; mi++) {
        int r0 = warp_m * 64 + mi * 16 + g;
#pragma unroll
        for (int ni = 0; ni < 4; ni++) {
            int n0 = warp_n * 32 + ni * 8 + tg * 2;
            float2 o0 = {acc[mi][ni][0], acc[mi][ni][1]};
            float2 o1 = {acc[mi][ni][2], acc[mi][ni][3]};
            *(float2*)(Sb + (size_t)(q0 + r0) * Tt + k0t + n0) = o0;
            *(float2*)(Sb + (size_t)(q0 + r0 + 8) * Tt + k0t + n0) = o1;
        }
    }

    __syncthreads();   // reuse sred
    if (tg == 0) {
#pragma unroll
        for (int mi = 0; mi < 4; mi++) {
            sred[warp_m * 64 + mi * 16 + g][warp_n] = mx[mi][0];
            sred[warp_m * 64 + mi * 16 + g + 8][warp_n] = mx[mi][1];
        }
    }
    __syncthreads();
    if (tid < 128) {
        float s4 = sred[tid][0] + sred[tid][1] + sred[tid][2] + sred[tid][3];
        size_t idx = (((size_t)bh * Tt + q0 + tid) * 16 + (k0t >> 7)) * 2;
        g_tilestats[idx] = sredm[tid];
        g_tilestats[idx + 1] = s4;
    }
}

// ---------------------------------------------------------------------------
// PV: prologue combines tile stats into per-(row,ktile) factors f = exp(mt-m)/l.
// Mainloop (cp.async 3-stage): P = E * f written in place (final attn_w);
// fragments scaled at load; accumulate P@V.
// ---------------------------------------------------------------------------
__global__ __launch_bounds__(256) void pv_tf32(float* __restrict__ S)
{
    extern __shared__ float dyn[];
    constexpr int STG_F = 128 * 20 + 16 * 64;   // 3584 floats/stage
    float* sf = dyn + 3 * STG_F;                // [128][16] factors

    const int qt = (Tt / 128 - 1) - blockIdx.x;    // heavy tiles first
    const int q0 = qt * 128;
    const int bh = blockIdx.y;
    const int b = bh / Hh, h = bh % Hh;
    const int tid = threadIdx.x, wid = tid >> 5, lane = tid & 31;
    const int g = lane >> 2, tg = lane & 3;
    const int warp_m = wid >> 1, warp_n = wid & 1;
    const int nkt = qt + 1;

    // prologue: per-row stats -> factors
    if (tid < 128) {
        const float* st = g_tilestats + ((size_t)bh * Tt + q0 + tid) * 32;
        float m = -INFINITY;
        for (int kt = 0; kt < nkt; kt++) m = fmaxf(m, st[kt * 2]);
        float l = 0.f;
        for (int kt = 0; kt < nkt; kt++) l += st[kt * 2 + 1] * __expf(st[kt * 2] - m);
        const float inv = 1.0f / l;
        for (int kt = 0; kt < nkt; kt++) sf[tid * 16 + kt] = __expf(st[kt * 2] - m) * inv;
    }

    float* Sb = S + (size_t)bh * Tt * Tt + (size_t)q0 * Tt;
    const float* Vb = g_qkv + (size_t)(b * Tt) * C3 + 2 * Cc + h * Dd;
    const uint32_t shbase = (uint32_t)__cvta_generic_to_shared(dyn);

    auto issue = [&](int s, int j) {
        const int k0 = j * 16;
#pragma unroll
        for (int i = 0; i < 2; i++) {
            int c = tid + i * 256;
            int r = c >> 2, col = (c & 3) * 4;
            cpasync16(shbase + (s * STG_F + r * 20 + col) * 4,
                      Sb + (size_t)r * Tt + k0 + col);
        }
        {
            int vk = tid >> 4, col = (tid & 15) * 4;
            int nx = col ^ ((vk & 3) << 3);
            cpasync16(shbase + (s * STG_F + 128 * 20 + vk * 64 + nx) * 4,
                      Vb + (size_t)(k0 + vk) * C3 + col);
        }
        asm volatile("cp.async.commit_group;\n");
    };

    const int nIter = nkt * 8;   // (q0+128)/16
    issue(0, 0);
    issue(1, 1);
    __syncthreads();   // also covers sf readiness

    const int wr = tid >> 1;                 // P writeback row
    const int wc = (tid & 1) * 8;            // P writeback col base

    float acc[2][4][4] = {};
    for (int j = 0; j < nIter; j++) {
        if (j == nIter - 1) {
            asm volatile("cp.async.wait_group 0;\n");
        } else {
            asm volatile("cp.async.wait_group 1;\n");
        }
        __syncthreads();
        const float* Ej = dyn + (j % 3) * STG_F;
        const float* Vj = Ej + 128 * 20;
        const int kt = j >> 3;

        // fragment rows' factors
        float fr[2][2];
#pragma unroll
        for (int mi = 0; mi < 2; mi++) {
            int m = warp_m * 32 + mi * 16;
            fr[mi][0] = sf[(m + g) * 16 + kt];
            fr[mi][1] = sf[(m + g + 8) * 16 + kt];
        }

#pragma unroll
        for (int ks = 0; ks < 16; ks += 8) {
            uint32_t af[2][4], bf[4][2];
#pragma unroll
            for (int mi = 0; mi < 2; mi++) {
                int m = warp_m * 32 + mi * 16;
                af[mi][0] = f2tf(Ej[(m + g) * 20 + ks + tg] * fr[mi][0]);
                af[mi][1] = f2tf(Ej[(m + g + 8) * 20 + ks + tg] * fr[mi][1]);
                af[mi][2] = f2tf(Ej[(m + g) * 20 + ks + tg + 4] * fr[mi][0]);
                af[mi][3] = f2tf(Ej[(m + g + 8) * 20 + ks + tg + 4] * fr[mi][1]);
            }
            const int xr = tg << 3;
#pragma unroll
            for (int ni = 0; ni < 4; ni++) {
                int n = warp_n * 32 + ni * 8;
                bf[ni][0] = f2tf(Vj[(ks + tg) * 64 + ((n + g) ^ xr)]);
                bf[ni][1] = f2tf(Vj[(ks + tg + 4) * 64 + ((n + g) ^ xr)]);
            }
#pragma unroll
            for (int mi = 0; mi < 2; mi++)
#pragma unroll
                for (int ni = 0; ni < 4; ni++) mma8(acc[mi][ni], af[mi], bf[ni]);
        }

        // P writeback (final attn_w): 8 values per thread
        {
            const float f = sf[wr * 16 + kt];
            float4 e0 = *(const float4*)(Ej + wr * 20 + wc);
            float4 e1 = *(const float4*)(Ej + wr * 20 + wc + 4);
            float4 p0 = {e0.x * f, e0.y * f, e0.z * f, e0.w * f};
            float4 p1 = {e1.x * f, e1.y * f, e1.z * f, e1.w * f};
            float* dst = Sb + (size_t)wr * Tt + j * 16 + wc;
            *(float4*)dst = p0;
            *(float4*)(dst + 4) = p1;
        }

        if (j + 2 < nIter) issue((j + 2) % 3, j + 2);
    }

#pragma unroll
    for (int mi = 0; mi < 2; mi++) {
#pragma unroll
        for (int ni = 0; ni < 4; ni++) {
            int q = q0 + warp_m * 32 + mi * 16 + g;
            int n = warp_n * 32 + ni * 8 + tg * 2;
            float* dst0 = g_attnv + (size_t)(b * Tt + q) * Cc + h * Dd + n;
            float* dst1 = g_attnv + (size_t)(b * Tt + q + 8) * Cc + h * Dd + n;
            *(float2*)dst0 = {acc[mi][ni][0], acc[mi][ni][1]};
            *(float2*)dst1 = {acc[mi][ni][2], acc[mi][ni][3]};
        }
    }
}

// ---------------------------------------------------------------------------
extern "C" void kernel_launch(void* const* d_in, const int* in_sizes, int n_in,
                              void* d_out, int out_size)
{
    const float* x     = (const float*)d_in[0];
    const float* w_qkv = (const float*)d_in[1];
    const float* b_qkv = (const float*)d_in[2];
    const float* w_o   = (const float*)d_in[3];
    const float* b_o   = (const float*)d_in[4];

    float* out   = (float*)d_out;
    float* attnw = out + (size_t)Mrows * Cc;   // [o | attn_w]

    float* qkv_ptr   = nullptr;
    float* attnv_ptr = nullptr;
    cudaGetSymbolAddress((void**)&qkv_ptr,   g_qkv);
    cudaGetSymbolAddress((void**)&attnv_ptr, g_attnv);

    const int gemm_smem   = 3 * (128 * 20 + 16 * 128) * 4;          // 55296
    const int scores_smem = 2 * 128 * 68 * 4;                       // 69632
    const int pv_smem     = (3 * (128 * 20 + 16 * 64) + 128 * 16) * 4; // 51200
    static bool attr_set = false;
    if (!attr_set) {
        cudaFuncSetAttribute(gemm_nn_tf32, cudaFuncAttributeMaxDynamicSharedMemorySize,
                             gemm_smem);
        cudaFuncSetAttribute(scores_tf32, cudaFuncAttributeMaxDynamicSharedMemorySize,
                             scores_smem);
        cudaFuncSetAttribute(pv_tf32, cudaFuncAttributeMaxDynamicSharedMemorySize,
                             pv_smem);
        attr_set = true;
    }

    // 1) QKV projection
    {
        dim3 grid(C3 / 128, Mrows / 128);
        gemm_nn_tf32<<<grid, 256, gemm_smem>>>(x, Cc, w_qkv, C3, b_qkv, qkv_ptr, C3, Cc);
    }
    // 2) Scores -> E + tile stats (upper tiles -> final zeros)
    {
        dim3 grid(Tt / 128, Tt / 128, BH);
        scores_tf32<<<grid, 256, scores_smem>>>(attnw);
    }
    // 3) P @ V, normalization fused (writes final attn_w in place)
    {
        dim3 grid(Tt / 128, BH);
        pv_tf32<<<grid, 256, pv_smem>>>(attnw);
    }
    // 4) Output projection
    {
        dim3 grid(Cc / 128, Mrows / 128);
        gemm_nn_tf32<<<grid, 256, gemm_smem>>>(attnv_ptr, Cc, w_o, Cc, b_o, out, Cc, Cc);
    }
}